// round 14
// baseline (speedup 1.0000x reference)
#include <cuda_runtime.h>
#include <cuda_bf16.h>
#include <cuda_fp8.h>
#include <cstdint>

#define B_SZ 8192
#define D_SZ 256

// ---------------- device scratch ----------------
__device__ unsigned char g_An8[B_SZ * D_SZ];   // normalized audio * 16, e4m3
__device__ unsigned char g_Tn8[B_SZ * D_SZ];   // normalized text  * 16, e4m3
__device__ unsigned g_rowmax[B_SZ];
__device__ unsigned g_colmax[B_SZ];
__device__ float    g_diag[B_SZ];              // exact fp32 diag

// Order-preserving float<->uint encoding for atomicMax on floats.
__device__ __forceinline__ unsigned fenc(float f) {
    unsigned u = __float_as_uint(f);
    return (u & 0x80000000u) ? ~u : (u | 0x80000000u);
}
__device__ __forceinline__ float fdec(unsigned u) {
    return (u & 0x80000000u) ? __uint_as_float(u ^ 0x80000000u) : __uint_as_float(~u);
}

// ---------------- fused: normalize -> fp8(e4m3, x16), exact diag, init ----------------
__global__ void prep_kernel(const float* __restrict__ A,
                            const float* __restrict__ T) {
    int g = blockIdx.x * 256 + threadIdx.x;
    if (g < B_SZ) {
        unsigned s = fenc(-3e38f);
        g_rowmax[g] = s;
        g_colmax[g] = s;
    }

    int row  = blockIdx.x * 8 + (threadIdx.x >> 5);
    int lane = threadIdx.x & 31;
    const float* a = A + (size_t)row * D_SZ;
    const float* t = T + (size_t)row * D_SZ;

    float4 a0 = ((const float4*)a)[2 * lane];
    float4 a1 = ((const float4*)a)[2 * lane + 1];
    float4 t0 = ((const float4*)t)[2 * lane];
    float4 t1 = ((const float4*)t)[2 * lane + 1];

    float sa = a0.x*a0.x + a0.y*a0.y + a0.z*a0.z + a0.w*a0.w
             + a1.x*a1.x + a1.y*a1.y + a1.z*a1.z + a1.w*a1.w;
    float st = t0.x*t0.x + t0.y*t0.y + t0.z*t0.z + t0.w*t0.w
             + t1.x*t1.x + t1.y*t1.y + t1.z*t1.z + t1.w*t1.w;
    float dt = a0.x*t0.x + a0.y*t0.y + a0.z*t0.z + a0.w*t0.w
             + a1.x*t1.x + a1.y*t1.y + a1.z*t1.z + a1.w*t1.w;
    #pragma unroll
    for (int o = 16; o > 0; o >>= 1) {
        sa += __shfl_xor_sync(0xffffffffu, sa, o);
        st += __shfl_xor_sync(0xffffffffu, st, o);
        dt += __shfl_xor_sync(0xffffffffu, dt, o);
    }
    float ka = 16.0f / sqrtf(sa);
    float kt = 16.0f / sqrtf(st);

    if (lane == 0) g_diag[row] = dt / (sqrtf(sa) * sqrtf(st));

    {
        __nv_fp8x4_e4m3 p0(make_float4(a0.x * ka, a0.y * ka, a0.z * ka, a0.w * ka));
        __nv_fp8x4_e4m3 p1(make_float4(a1.x * ka, a1.y * ka, a1.z * ka, a1.w * ka));
        uint2 o2;
        o2.x = (unsigned)p0.__x;
        o2.y = (unsigned)p1.__x;
        *(uint2*)(g_An8 + (size_t)row * D_SZ + lane * 8) = o2;
    }
    {
        __nv_fp8x4_e4m3 p0(make_float4(t0.x * kt, t0.y * kt, t0.z * kt, t0.w * kt));
        __nv_fp8x4_e4m3 p1(make_float4(t1.x * kt, t1.y * kt, t1.z * kt, t1.w * kt));
        uint2 o2;
        o2.x = (unsigned)p0.__x;
        o2.y = (unsigned)p1.__x;
        *(uint2*)(g_Tn8 + (size_t)row * D_SZ + lane * 8) = o2;
    }
}

// ---------------- FP8 single-shot GEMM + masked row/col max ----------------
// CTA tile 64x64, FULL K=256 in smem (A 16KB + B 16KB), 128 threads,
// 4 warps (2x2 grid of 32x32 warp tiles). ONE load burst, ONE syncthreads,
// barrier-free MMA burst. 6 CTAs/SM -> 24 warps/SM (the new lever).

#define SM_A     0
#define SM_B     16384
#define SM_LABR  32768            // 64 * 8
#define SM_LABC  33280            // 64 * 8
#define SM_RMAX  33792            // 64 * 4
#define SM_CMAX  34048            // 64 * 4
#define DYN_SMEM 34560

#define INV_SCALE (1.0f / 256.0f)

__device__ __forceinline__ void cp_async16(uint32_t saddr, const void* gaddr) {
    asm volatile("cp.async.cg.shared.global [%0], [%1], 16;" :: "r"(saddr), "l"(gaddr));
}
__device__ __forceinline__ void ldm_x4(uint32_t (&r)[4], uint32_t addr) {
    asm volatile("ldmatrix.sync.aligned.m8n8.x4.shared.b16 {%0,%1,%2,%3}, [%4];"
                 : "=r"(r[0]), "=r"(r[1]), "=r"(r[2]), "=r"(r[3]) : "r"(addr));
}
__device__ __forceinline__ void mma_fp8(float (&c)[4], const uint32_t (&a)[4],
                                        uint32_t b0, uint32_t b1) {
    asm volatile("mma.sync.aligned.m16n8k32.row.col.f32.e4m3.e4m3.f32 "
                 "{%0,%1,%2,%3}, {%4,%5,%6,%7}, {%8,%9}, {%0,%1,%2,%3};"
                 : "+f"(c[0]), "+f"(c[1]), "+f"(c[2]), "+f"(c[3])
                 : "r"(a[0]), "r"(a[1]), "r"(a[2]), "r"(a[3]), "r"(b0), "r"(b1));
}

// 256B rows; 16B group index grp 0..15; swizzle low 3 group bits by row&7.
__device__ __forceinline__ int swz(int row, int grp) {
    return row * 256 + ((grp ^ (row & 7)) << 4);
}

__global__ void __launch_bounds__(128, 6)
gemm_max_kernel(const long long* __restrict__ labels) {
    extern __shared__ __align__(1024) char sm[];

    const int tid  = threadIdx.x;
    const int w    = tid >> 5;
    const int lane = tid & 31;
    const int wm   = w >> 1;        // 0..1 -> 32-row band
    const int wn   = w & 1;         // 0..1 -> 32-col band
    const int bx   = blockIdx.x;    // N tile (text, 64 cols)
    const int by   = blockIdx.y;    // M tile (audio, 64 rows)

    long long* sLr = (long long*)(sm + SM_LABR);
    long long* sLc = (long long*)(sm + SM_LABC);
    unsigned*  s_rmax = (unsigned*)(sm + SM_RMAX);
    unsigned*  s_cmax = (unsigned*)(sm + SM_CMAX);

    if (tid < 64) {
        unsigned s = fenc(-3e38f);
        s_rmax[tid] = s;
        s_cmax[tid] = s;
        sLr[tid] = labels[by * 64 + tid];
        sLc[tid] = labels[bx * 64 + tid];
    }

    const unsigned char* Ag = g_An8 + (size_t)(by * 64) * D_SZ;
    const unsigned char* Bg = g_Tn8 + (size_t)(bx * 64) * D_SZ;
    const uint32_t smb = (uint32_t)__cvta_generic_to_shared(sm);
    const uint32_t sa = smb + SM_A;
    const uint32_t sb = smb + SM_B;

    // ---- single load burst: A + B (1024 16B chunks each; 8/thread each) ----
    #pragma unroll
    for (int p = 0; p < 8; ++p) {
        int c = p * 128 + tid;            // 0..1023
        int row = c >> 4, grp = c & 15;
        int so = swz(row, grp);
        const size_t go = (size_t)row * D_SZ + grp * 16;
        cp_async16(sa + so, Ag + go);
        cp_async16(sb + so, Bg + go);
    }
    asm volatile("cp.async.commit_group;");

    float acc[2][4][4];
    #pragma unroll
    for (int i = 0; i < 2; i++)
        #pragma unroll
        for (int j = 0; j < 4; j++)
            #pragma unroll
            for (int e = 0; e < 4; e++) acc[i][j][e] = 0.0f;

    asm volatile("cp.async.wait_group 0;");
    __syncthreads();

    // ---- barrier-free MMA burst: 8 k-steps (k32 each) ----
    const int lrow = lane & 15;
    const int lhi  = lane >> 4;

    #pragma unroll
    for (int ks = 0; ks < 8; ++ks) {
        const int grp = ks * 2 + lhi;     // 16B group; pair spans 32B = k32
        uint32_t a[2][4];
        #pragma unroll
        for (int mf = 0; mf < 2; ++mf) {
            int row = wm * 32 + mf * 16 + lrow;
            ldm_x4(a[mf], sa + swz(row, grp));
        }
        uint32_t b[4][2];
        #pragma unroll
        for (int np = 0; np < 2; ++np) {
            int row = wn * 32 + np * 16 + lrow;
            uint32_t r[4];
            ldm_x4(r, sb + swz(row, grp));
            b[np * 2 + 0][0] = r[0];
            b[np * 2 + 1][0] = r[1];
            b[np * 2 + 0][1] = r[2];
            b[np * 2 + 1][1] = r[3];
        }
        #pragma unroll
        for (int mf = 0; mf < 2; ++mf)
            #pragma unroll
            for (int nf = 0; nf < 4; ++nf)
                mma_fp8(acc[mf][nf], a[mf], b[nf][0], b[nf][1]);
    }

    // ---- epilogue: masked row/col max (undo 256x scale at the max) ----
    const int qr = lane >> 2;        // 0..7
    const int qc = (lane & 3) * 2;   // 0,2,4,6

    #pragma unroll
    for (int mf = 0; mf < 2; ++mf) {
        #pragma unroll
        for (int h = 0; h < 2; ++h) {
            int rloc = wm * 32 + mf * 16 + qr + h * 8;
            long long labR = sLr[rloc];
            float rm = -3e38f;
            #pragma unroll
            for (int nf = 0; nf < 4; ++nf) {
                int cl = wn * 32 + nf * 8 + qc;
                float v0 = acc[mf][nf][h * 2 + 0];
                float v1 = acc[mf][nf][h * 2 + 1];
                if (labR != sLc[cl])     rm = fmaxf(rm, v0);
                if (labR != sLc[cl + 1]) rm = fmaxf(rm, v1);
            }
            rm = fmaxf(rm * INV_SCALE, -3e38f);
            atomicMax(&s_rmax[rloc], fenc(rm));
        }
    }
    #pragma unroll
    for (int nf = 0; nf < 4; ++nf) {
        int cl = wn * 32 + nf * 8 + qc;
        long long lc0 = sLc[cl], lc1 = sLc[cl + 1];
        float cm0 = -3e38f, cm1 = -3e38f;
        #pragma unroll
        for (int mf = 0; mf < 2; ++mf) {
            #pragma unroll
            for (int h = 0; h < 2; ++h) {
                int rloc = wm * 32 + mf * 16 + qr + h * 8;
                long long labR = sLr[rloc];
                float v0 = acc[mf][nf][h * 2 + 0];
                float v1 = acc[mf][nf][h * 2 + 1];
                if (labR != lc0) cm0 = fmaxf(cm0, v0);
                if (labR != lc1) cm1 = fmaxf(cm1, v1);
            }
        }
        cm0 = fmaxf(cm0 * INV_SCALE, -3e38f);
        cm1 = fmaxf(cm1 * INV_SCALE, -3e38f);
        atomicMax(&s_cmax[cl],     fenc(cm0));
        atomicMax(&s_cmax[cl + 1], fenc(cm1));
    }

    __syncthreads();
    if (tid < 64) {
        atomicMax(&g_rowmax[by * 64 + tid], s_rmax[tid]);
        atomicMax(&g_colmax[bx * 64 + tid], s_cmax[tid]);
    }
}

// ---------------- single-block loss + reduction ----------------
__device__ __forceinline__ float loss_term(float d, float m) {
    bool valid = (d < 1.0f - 1e-5f) && (m + 0.2f > d);
    if (!valid) return 0.0f;
    float pl = fmaxf(0.2f * d * d - 0.7f * d + 0.5f, 0.0f);
    float nl = fmaxf(0.9f * m * m - 0.4f * m + 0.03f, 0.0f);
    return pl + nl;
}

__global__ void loss_final_kernel(float* __restrict__ out) {
    __shared__ float sdata[256];
    float c = 0.0f;
    for (int i = threadIdx.x; i < B_SZ; i += 256) {
        float d  = g_diag[i];
        float mr = fdec(g_rowmax[i]);
        float mc = fdec(g_colmax[i]);
        c += loss_term(d, mr) + loss_term(d, mc);
    }
    sdata[threadIdx.x] = c;
    __syncthreads();
    #pragma unroll
    for (int s = 128; s > 0; s >>= 1) {
        if (threadIdx.x < s) sdata[threadIdx.x] += sdata[threadIdx.x + s];
        __syncthreads();
    }
    if (threadIdx.x == 0) out[0] = sdata[0] / (float)B_SZ;
}

// ---------------- launch ----------------
extern "C" void kernel_launch(void* const* d_in, const int* in_sizes, int n_in,
                              void* d_out, int out_size) {
    const float*     A      = (const float*)d_in[0];
    const float*     T      = (const float*)d_in[1];
    const long long* labels = (const long long*)d_in[2];
    float*           out    = (float*)d_out;

    cudaFuncSetAttribute(gemm_max_kernel,
                         cudaFuncAttributeMaxDynamicSharedMemorySize, DYN_SMEM);

    prep_kernel<<<B_SZ / 8, 256>>>(A, T);
    gemm_max_kernel<<<dim3(B_SZ / 64, B_SZ / 64), 128, DYN_SMEM>>>(labels);
    loss_final_kernel<<<1, 256>>>(out);
}

// round 15
// speedup vs baseline: 1.2037x; 1.2037x over previous
#include <cuda_runtime.h>
#include <cuda_bf16.h>
#include <cstdint>

#define B_SZ 8192
#define D_SZ 256

// ---------------- device scratch ----------------
__device__ unsigned short g_Anb[B_SZ * D_SZ];   // normalized audio, bf16
__device__ unsigned short g_Tnb[B_SZ * D_SZ];   // normalized text, bf16
__device__ unsigned g_rowmax[B_SZ];
__device__ unsigned g_colmax[B_SZ];
__device__ float    g_diag[B_SZ];               // exact fp32 diag
__device__ float    g_partial[32];

// Order-preserving float<->uint encoding for atomicMax on floats.
__device__ __forceinline__ unsigned fenc(float f) {
    unsigned u = __float_as_uint(f);
    return (u & 0x80000000u) ? ~u : (u | 0x80000000u);
}
__device__ __forceinline__ float fdec(unsigned u) {
    return (u & 0x80000000u) ? __uint_as_float(u ^ 0x80000000u) : __uint_as_float(~u);
}

// ---------------- fused: normalize -> bf16, exact diag, sentinel init ----------------
__global__ void prep_kernel(const float* __restrict__ A,
                            const float* __restrict__ T) {
    int g = blockIdx.x * 256 + threadIdx.x;
    if (g < B_SZ) {
        unsigned s = fenc(-3e38f);
        g_rowmax[g] = s;
        g_colmax[g] = s;
    }

    int row  = blockIdx.x * 8 + (threadIdx.x >> 5);
    int lane = threadIdx.x & 31;
    const float* a = A + (size_t)row * D_SZ;
    const float* t = T + (size_t)row * D_SZ;

    float4 a0 = ((const float4*)a)[2 * lane];
    float4 a1 = ((const float4*)a)[2 * lane + 1];
    float4 t0 = ((const float4*)t)[2 * lane];
    float4 t1 = ((const float4*)t)[2 * lane + 1];

    float sa = a0.x*a0.x + a0.y*a0.y + a0.z*a0.z + a0.w*a0.w
             + a1.x*a1.x + a1.y*a1.y + a1.z*a1.z + a1.w*a1.w;
    float st = t0.x*t0.x + t0.y*t0.y + t0.z*t0.z + t0.w*t0.w
             + t1.x*t1.x + t1.y*t1.y + t1.z*t1.z + t1.w*t1.w;
    float dt = a0.x*t0.x + a0.y*t0.y + a0.z*t0.z + a0.w*t0.w
             + a1.x*t1.x + a1.y*t1.y + a1.z*t1.z + a1.w*t1.w;
    #pragma unroll
    for (int o = 16; o > 0; o >>= 1) {
        sa += __shfl_xor_sync(0xffffffffu, sa, o);
        st += __shfl_xor_sync(0xffffffffu, st, o);
        dt += __shfl_xor_sync(0xffffffffu, dt, o);
    }
    float ra = 1.0f / sqrtf(sa);
    float rt = 1.0f / sqrtf(st);

    if (lane == 0) g_diag[row] = dt / (sqrtf(sa) * sqrtf(st));

    {
        __nv_bfloat162 b0 = __floats2bfloat162_rn(a0.x * ra, a0.y * ra);
        __nv_bfloat162 b1 = __floats2bfloat162_rn(a0.z * ra, a0.w * ra);
        __nv_bfloat162 b2 = __floats2bfloat162_rn(a1.x * ra, a1.y * ra);
        __nv_bfloat162 b3 = __floats2bfloat162_rn(a1.z * ra, a1.w * ra);
        uint4 o4;
        o4.x = *(unsigned*)&b0; o4.y = *(unsigned*)&b1;
        o4.z = *(unsigned*)&b2; o4.w = *(unsigned*)&b3;
        *(uint4*)(g_Anb + (size_t)row * D_SZ + lane * 8) = o4;
    }
    {
        __nv_bfloat162 b0 = __floats2bfloat162_rn(t0.x * rt, t0.y * rt);
        __nv_bfloat162 b1 = __floats2bfloat162_rn(t0.z * rt, t0.w * rt);
        __nv_bfloat162 b2 = __floats2bfloat162_rn(t1.x * rt, t1.y * rt);
        __nv_bfloat162 b3 = __floats2bfloat162_rn(t1.z * rt, t1.w * rt);
        uint4 o4;
        o4.x = *(unsigned*)&b0; o4.y = *(unsigned*)&b1;
        o4.z = *(unsigned*)&b2; o4.w = *(unsigned*)&b3;
        *(uint4*)(g_Tnb + (size_t)row * D_SZ + lane * 8) = o4;
    }
}

// ---------------- warp-MMA GEMM + masked row/col max (round-5 proven mainloop) ----------------
// CTA tile 128x128, BK=32, 256 threads (8 warps, 2x4), 64x32 per warp.
// 3-stage cp.async ring, ONE __syncthreads per k-tile, loads before compute.

#define BK 32
#define TILE_BYTES 8192                      // 128 rows x 64B
#define STG_BYTES  (2 * TILE_BYTES)
#define NSTG 3
#define SM_LABR  (NSTG * STG_BYTES)          // 49152
#define SM_LABC  (SM_LABR + 1024)
#define SM_RMAX  (SM_LABC + 1024)
#define SM_CMAX  (SM_RMAX + 512)
#define DYN_SMEM (SM_CMAX + 512)             // 52224

__device__ __forceinline__ void cp_async16(uint32_t saddr, const void* gaddr) {
    asm volatile("cp.async.cg.shared.global [%0], [%1], 16;" :: "r"(saddr), "l"(gaddr));
}
__device__ __forceinline__ void ldm_x4(uint32_t (&r)[4], uint32_t addr) {
    asm volatile("ldmatrix.sync.aligned.m8n8.x4.shared.b16 {%0,%1,%2,%3}, [%4];"
                 : "=r"(r[0]), "=r"(r[1]), "=r"(r[2]), "=r"(r[3]) : "r"(addr));
}
__device__ __forceinline__ void mma_bf16(float (&c)[4], const uint32_t (&a)[4],
                                         uint32_t b0, uint32_t b1) {
    asm volatile("mma.sync.aligned.m16n8k16.row.col.f32.bf16.bf16.f32 "
                 "{%0,%1,%2,%3}, {%4,%5,%6,%7}, {%8,%9}, {%0,%1,%2,%3};"
                 : "+f"(c[0]), "+f"(c[1]), "+f"(c[2]), "+f"(c[3])
                 : "r"(a[0]), "r"(a[1]), "r"(a[2]), "r"(a[3]), "r"(b0), "r"(b1));
}

__global__ void __launch_bounds__(256, 2)
gemm_max_kernel(const long long* __restrict__ labels) {
    extern __shared__ __align__(1024) char sm[];

    const int tid  = threadIdx.x;
    const int w    = tid >> 5;
    const int lane = tid & 31;
    const int wm   = w >> 2;        // 0..1
    const int wn   = w & 3;         // 0..3
    const int bx   = blockIdx.x;    // N tile (text)
    const int by   = blockIdx.y;    // M tile (audio)

    long long* sLr = (long long*)(sm + SM_LABR);
    long long* sLc = (long long*)(sm + SM_LABC);
    unsigned*  s_rmax = (unsigned*)(sm + SM_RMAX);
    unsigned*  s_cmax = (unsigned*)(sm + SM_CMAX);

    if (tid < 128) {
        unsigned s = fenc(-3e38f);
        s_rmax[tid] = s;
        s_cmax[tid] = s;
        sLr[tid] = labels[by * 128 + tid];
        sLc[tid] = labels[bx * 128 + tid];
    }

    float acc[4][4][4];
    #pragma unroll
    for (int i = 0; i < 4; i++)
        #pragma unroll
        for (int j = 0; j < 4; j++)
            #pragma unroll
            for (int e = 0; e < 4; e++) acc[i][j][e] = 0.0f;

    const unsigned short* Ag = g_Anb + (size_t)(by * 128) * D_SZ;
    const unsigned short* Bg = g_Tnb + (size_t)(bx * 128) * D_SZ;
    const uint32_t smb = (uint32_t)__cvta_generic_to_shared(sm);

    auto swz = [](int row, int grp) -> int {
        return row * 64 + ((grp ^ ((row >> 1) & 3)) << 4);
    };

    auto load_stage = [&](int st, int kt) {
        int kofs = kt * BK;
        uint32_t sa = smb + st * STG_BYTES;
        uint32_t sb = sa + TILE_BYTES;
        #pragma unroll
        for (int p = 0; p < 2; ++p) {
            int c = p * 256 + tid;
            int row = c >> 2, grp = c & 3;
            int so = swz(row, grp);
            cp_async16(sa + so, Ag + (size_t)row * D_SZ + kofs + grp * 8);
            cp_async16(sb + so, Bg + (size_t)row * D_SZ + kofs + grp * 8);
        }
    };

    load_stage(0, 0);
    asm volatile("cp.async.commit_group;");
    load_stage(1, 1);
    asm volatile("cp.async.commit_group;");

    const int lrow = lane & 15;
    const int lhi  = lane >> 4;

    #pragma unroll
    for (int kt = 0; kt < 8; ++kt) {
        asm volatile("cp.async.wait_group 1;");
        __syncthreads();

        if (kt < 6) load_stage((kt + 2) % NSTG, kt + 2);
        asm volatile("cp.async.commit_group;");

        const int s = kt % NSTG;
        const uint32_t sa = smb + s * STG_BYTES;
        const uint32_t sb = sa + TILE_BYTES;

        #pragma unroll
        for (int ks = 0; ks < 2; ++ks) {
            const int grp = ks * 2 + lhi;
            uint32_t a[4][4];
            #pragma unroll
            for (int mf = 0; mf < 4; ++mf) {
                int row = wm * 64 + mf * 16 + lrow;
                ldm_x4(a[mf], sa + swz(row, grp));
            }
            uint32_t b[4][2];
            #pragma unroll
            for (int np = 0; np < 2; ++np) {
                int row = wn * 32 + np * 16 + lrow;
                uint32_t r[4];
                ldm_x4(r, sb + swz(row, grp));
                b[np * 2 + 0][0] = r[0];
                b[np * 2 + 1][0] = r[1];
                b[np * 2 + 0][1] = r[2];
                b[np * 2 + 1][1] = r[3];
            }
            #pragma unroll
            for (int mf = 0; mf < 4; ++mf)
                #pragma unroll
                for (int nf = 0; nf < 4; ++nf)
                    mma_bf16(acc[mf][nf], a[mf], b[nf][0], b[nf][1]);
        }
    }

    // ---- epilogue: masked row/col max with quad shuffle pre-reduction ----
    const int qr = lane >> 2;        // 0..7 (row within 8-row group)
    const int qc = (lane & 3) * 2;   // 0,2,4,6 (col pair within 8)

    // Row maxima: threads with same qr (lane>>2) but different (lane&3) hold
    // the same rows; combine across the quad via shfl_xor(1), shfl_xor(2),
    // then one atomic per row by the quad leader.
    #pragma unroll
    for (int mf = 0; mf < 4; ++mf) {
        #pragma unroll
        for (int h = 0; h < 2; ++h) {
            int rloc = wm * 64 + mf * 16 + qr + h * 8;
            long long labR = sLr[rloc];
            float rm = -3e38f;
            #pragma unroll
            for (int nf = 0; nf < 4; ++nf) {
                int cl = wn * 32 + nf * 8 + qc;
                float v0 = acc[mf][nf][h * 2 + 0];
                float v1 = acc[mf][nf][h * 2 + 1];
                if (labR != sLc[cl])     rm = fmaxf(rm, v0);
                if (labR != sLc[cl + 1]) rm = fmaxf(rm, v1);
            }
            rm = fmaxf(rm, __shfl_xor_sync(0xffffffffu, rm, 1));
            rm = fmaxf(rm, __shfl_xor_sync(0xffffffffu, rm, 2));
            if ((lane & 3) == 0) atomicMax(&s_rmax[rloc], fenc(rm));
        }
    }
    // Col maxima: threads with same (lane&3) but different qr hold the same
    // cols; combine across qr via shfl_xor(4,8,16), one atomic per col pair.
    #pragma unroll
    for (int nf = 0; nf < 4; ++nf) {
        int cl = wn * 32 + nf * 8 + qc;
        long long lc0 = sLc[cl], lc1 = sLc[cl + 1];
        float cm0 = -3e38f, cm1 = -3e38f;
        #pragma unroll
        for (int mf = 0; mf < 4; ++mf) {
            #pragma unroll
            for (int h = 0; h < 2; ++h) {
                int rloc = wm * 64 + mf * 16 + qr + h * 8;
                long long labR = sLr[rloc];
                float v0 = acc[mf][nf][h * 2 + 0];
                float v1 = acc[mf][nf][h * 2 + 1];
                if (labR != lc0) cm0 = fmaxf(cm0, v0);
                if (labR != lc1) cm1 = fmaxf(cm1, v1);
            }
        }
        #pragma unroll
        for (int o = 4; o < 32; o <<= 1) {
            cm0 = fmaxf(cm0, __shfl_xor_sync(0xffffffffu, cm0, o));
            cm1 = fmaxf(cm1, __shfl_xor_sync(0xffffffffu, cm1, o));
        }
        if (qr == 0) {
            atomicMax(&s_cmax[cl],     fenc(cm0));
            atomicMax(&s_cmax[cl + 1], fenc(cm1));
        }
    }

    __syncthreads();
    if (tid < 128) {
        atomicMax(&g_rowmax[by * 128 + tid], s_rmax[tid]);
        atomicMax(&g_colmax[bx * 128 + tid], s_cmax[tid]);
    }
}

// ---------------- loss + reduction (round-5 measured pair) ----------------
__device__ __forceinline__ float loss_term(float d, float m) {
    bool valid = (d < 1.0f - 1e-5f) && (m + 0.2f > d);
    if (!valid) return 0.0f;
    float pl = fmaxf(0.2f * d * d - 0.7f * d + 0.5f, 0.0f);
    float nl = fmaxf(0.9f * m * m - 0.4f * m + 0.03f, 0.0f);
    return pl + nl;
}

__global__ void loss_kernel() {
    __shared__ float sdata[256];
    int i = blockIdx.x * 256 + threadIdx.x;
    float d  = g_diag[i];
    float mr = fdec(g_rowmax[i]);
    float mc = fdec(g_colmax[i]);
    float c  = loss_term(d, mr) + loss_term(d, mc);
    sdata[threadIdx.x] = c;
    __syncthreads();
    #pragma unroll
    for (int s = 128; s > 0; s >>= 1) {
        if (threadIdx.x < s) sdata[threadIdx.x] += sdata[threadIdx.x + s];
        __syncthreads();
    }
    if (threadIdx.x == 0) g_partial[blockIdx.x] = sdata[0];
}

__global__ void final_kernel(float* __restrict__ out) {
    float s = (threadIdx.x < 32) ? g_partial[threadIdx.x] : 0.0f;
    #pragma unroll
    for (int o = 16; o > 0; o >>= 1) s += __shfl_xor_sync(0xffffffffu, s, o);
    if (threadIdx.x == 0) out[0] = s / (float)B_SZ;
}

// ---------------- launch ----------------
extern "C" void kernel_launch(void* const* d_in, const int* in_sizes, int n_in,
                              void* d_out, int out_size) {
    const float*     A      = (const float*)d_in[0];
    const float*     T      = (const float*)d_in[1];
    const long long* labels = (const long long*)d_in[2];
    float*           out    = (float*)d_out;

    cudaFuncSetAttribute(gemm_max_kernel,
                         cudaFuncAttributeMaxDynamicSharedMemorySize, DYN_SMEM);

    prep_kernel<<<B_SZ / 8, 256>>>(A, T);
    gemm_max_kernel<<<dim3(B_SZ / 128, B_SZ / 128), 256, DYN_SMEM>>>(labels);
    loss_kernel<<<B_SZ / 256, 256>>>();
    final_kernel<<<1, 32>>>(out);
}